// round 2
// baseline (speedup 1.0000x reference)
#include <cuda_runtime.h>
#include <cstdint>

#define N_NODES 100000
#define N_EDGES 1600000
#define D 128
#define BM 64
#define WST 132   // padded k-major stride for W tiles (16B-aligned, conflict-free)

// scratch (no allocations allowed)
__device__ float g_msg[N_NODES * D];
__device__ float g_deg[N_NODES];
__device__ int   g_is64;   // 1 if edge_index is int64, 0 if int32

// ---------------------------------------------------------------------------
// Detect edge_index dtype: interpret as int64; if first 1024 values all lie in
// [0, N_NODES) it's int64, else int32 (int32 pairs viewed as int64 are >= 2^32
// unless the high word happens to be 0).
// ---------------------------------------------------------------------------
__global__ void detect_dtype_kernel(const long long* __restrict__ ei64) {
    int lane = threadIdx.x;
    int bad = 0;
    for (int i = lane; i < 1024; i += 32) {
        long long v = ei64[i];
        if (v < 0 || v >= N_NODES) bad = 1;
    }
    unsigned m = __ballot_sync(0xFFFFFFFFu, bad);
    if (lane == 0) g_is64 = (m == 0u) ? 1 : 0;
}

// ---------------------------------------------------------------------------
// Scatter: one warp per edge. Lane l handles float4 chunk l of the 128-wide row.
// red.global.add.v4.f32 = fire-and-forget L2 reduction, 1 instr per 16 B.
// ---------------------------------------------------------------------------
__global__ void scatter_kernel(const float* __restrict__ x,
                               const void* __restrict__ ei_raw,
                               float* __restrict__ msg,
                               float* __restrict__ deg) {
    int warp = (int)((blockIdx.x * (unsigned)blockDim.x + threadIdx.x) >> 5);
    int lane = threadIdx.x & 31;
    if (warp >= N_EDGES) return;

    long long src, dst;
    if (g_is64) {
        const long long* ei = (const long long*)ei_raw;
        src = ei[warp];
        dst = ei[N_EDGES + warp];
    } else {
        const int* ei = (const int*)ei_raw;
        src = ei[warp];
        dst = ei[N_EDGES + warp];
    }
    // defensive clamp (branch never taken on valid data)
    if ((unsigned long long)src >= N_NODES || (unsigned long long)dst >= N_NODES) return;

    float4 v = ((const float4*)(x + (size_t)src * D))[lane];
    float* p = msg + (size_t)dst * D + lane * 4;
    asm volatile("red.global.add.v4.f32 [%0], {%1,%2,%3,%4};"
                 :: "l"(p), "f"(v.x), "f"(v.y), "f"(v.z), "f"(v.w) : "memory");
    if (lane == 0) {
        asm volatile("red.global.add.f32 [%0], %1;"
                     :: "l"(deg + dst), "f"(1.0f) : "memory");
    }
}

// ---------------------------------------------------------------------------
// Fused: out[g] = relu( (msg[g]/max(deg,1)) @ Wl^T + b + x[g] @ Wr^T )
// Block: 64 nodes x all 128 out-cols. 256 threads.
// Warp w -> nodes w*8..w*8+7; lane -> 4 contiguous out-cols (float4 acc).
// smem: Wl,Wr transposed to [k][c] (stride 132), features natural [n][k].
// ---------------------------------------------------------------------------
__global__ void fused_gemm_kernel(const float* __restrict__ x,
                                  const float* __restrict__ Wl,
                                  const float* __restrict__ bias,
                                  const float* __restrict__ Wr,
                                  const float* __restrict__ msg,
                                  const float* __restrict__ deg,
                                  float* __restrict__ out) {
    extern __shared__ float sm[];
    float* sWl = sm;                       // [128][WST]
    float* sWr = sm + 128 * WST;           // [128][WST]
    float* sA  = sm + 2 * 128 * WST;       // [64][128]  agg (msg/deg)
    float* sX  = sA + BM * 128;            // [64][128]  x

    const int tid = threadIdx.x;
    const int n0blk = blockIdx.x * BM;

    // --- stage W transposed: idx -> (c = idx&127, kq = idx>>7). Lanes take
    // consecutive c -> conflict-free STS; LDG is strided but W is tiny & L2-hot.
    for (int idx = tid; idx < 128 * 32; idx += 256) {
        int c = idx & 127;
        int kq = idx >> 7;          // which float4 along k
        float4 wl = ((const float4*)(Wl + c * 128))[kq];
        float4 wr = ((const float4*)(Wr + c * 128))[kq];
        int k = kq * 4;
        sWl[(k + 0) * WST + c] = wl.x;
        sWl[(k + 1) * WST + c] = wl.y;
        sWl[(k + 2) * WST + c] = wl.z;
        sWl[(k + 3) * WST + c] = wl.w;
        sWr[(k + 0) * WST + c] = wr.x;
        sWr[(k + 1) * WST + c] = wr.y;
        sWr[(k + 2) * WST + c] = wr.z;
        sWr[(k + 3) * WST + c] = wr.w;
    }

    // --- stage features (natural layout, fully coalesced both sides)
    for (int idx = tid; idx < BM * 32; idx += 256) {
        int n = idx >> 5;
        int kq = idx & 31;
        int g = n0blk + n;
        float4 a = make_float4(0.f, 0.f, 0.f, 0.f);
        float4 xv = a;
        if (g < N_NODES) {
            xv = ((const float4*)(x + (size_t)g * D))[kq];
            float4 m = ((const float4*)(msg + (size_t)g * D))[kq];
            float inv = 1.0f / fmaxf(deg[g], 1.0f);
            a.x = m.x * inv; a.y = m.y * inv; a.z = m.z * inv; a.w = m.w * inv;
        }
        ((float4*)(sA + n * 128))[kq] = a;
        ((float4*)(sX + n * 128))[kq] = xv;
    }
    __syncthreads();

    const int lane = tid & 31;
    const int wrp = tid >> 5;
    const int c0 = lane * 4;
    const int n0 = wrp * 8;

    float4 bb = ((const float4*)bias)[lane];
    float4 acc[8];
#pragma unroll
    for (int j = 0; j < 8; j++) acc[j] = bb;

#pragma unroll 4
    for (int k = 0; k < 128; k++) {
        float4 wl = *(const float4*)(sWl + k * WST + c0);
        float4 wr = *(const float4*)(sWr + k * WST + c0);
#pragma unroll
        for (int j = 0; j < 8; j++) {
            float a  = sA[(n0 + j) * 128 + k];   // broadcast
            float xv = sX[(n0 + j) * 128 + k];   // broadcast
            acc[j].x = fmaf(a, wl.x, fmaf(xv, wr.x, acc[j].x));
            acc[j].y = fmaf(a, wl.y, fmaf(xv, wr.y, acc[j].y));
            acc[j].z = fmaf(a, wl.z, fmaf(xv, wr.z, acc[j].z));
            acc[j].w = fmaf(a, wl.w, fmaf(xv, wr.w, acc[j].w));
        }
    }

#pragma unroll
    for (int j = 0; j < 8; j++) {
        int g = n0blk + n0 + j;
        if (g < N_NODES) {
            float4 r;
            r.x = fmaxf(acc[j].x, 0.f);
            r.y = fmaxf(acc[j].y, 0.f);
            r.z = fmaxf(acc[j].z, 0.f);
            r.w = fmaxf(acc[j].w, 0.f);
            ((float4*)(out + (size_t)g * D))[lane] = r;
        }
    }
}

extern "C" void kernel_launch(void* const* d_in, const int* in_sizes, int n_in,
                              void* d_out, int out_size) {
    const float* x  = (const float*)d_in[0];
    const void*  ei = d_in[1];
    const float* Wl = (const float*)d_in[2];
    const float* bl = (const float*)d_in[3];
    const float* Wr = (const float*)d_in[4];
    float* out = (float*)d_out;

    float *msg, *deg;
    cudaGetSymbolAddress((void**)&msg, g_msg);
    cudaGetSymbolAddress((void**)&deg, g_deg);

    detect_dtype_kernel<<<1, 32>>>((const long long*)ei);

    cudaMemsetAsync(msg, 0, sizeof(float) * (size_t)N_NODES * D);
    cudaMemsetAsync(deg, 0, sizeof(float) * N_NODES);

    // one warp per edge
    int blocks = (N_EDGES * 32 + 255) / 256;
    scatter_kernel<<<blocks, 256>>>(x, ei, msg, deg);

    int smem = (2 * 128 * WST + 2 * BM * 128) * sizeof(float);  // 200704 B
    cudaFuncSetAttribute(fused_gemm_kernel,
                         cudaFuncAttributeMaxDynamicSharedMemorySize, smem);
    int gblocks = (N_NODES + BM - 1) / BM;
    fused_gemm_kernel<<<gblocks, 256, smem>>>(x, Wl, bl, Wr, msg, deg, out);
}

// round 4
// speedup vs baseline: 1.3053x; 1.3053x over previous
#include <cuda_runtime.h>
#include <cstdint>

#define N_NODES 100000
#define N_EDGES 1600000
#define D 128
#define GM 128            // nodes per GEMM CTA
#define SB_ST 260         // sB stride (floats): bank map (grp*4+thr), conflict-free
#define SA_ST 132         // sA stride (floats): same property

// ---- scratch (no allocations allowed) ----
__device__ float g_msg[N_NODES * D];
__device__ float g_deg[N_NODES];
__device__ int   g_is64;

__device__ __forceinline__ float to_tf32(float f) {
    float r; asm("cvt.rna.tf32.f32 %0, %1;" : "=f"(r) : "f"(f)); return r;
}

__device__ __forceinline__ void mma_tf32(float* c, const uint32_t* a,
                                         uint32_t b0, uint32_t b1) {
    asm volatile(
        "mma.sync.aligned.m16n8k8.row.col.f32.tf32.tf32.f32 "
        "{%0,%1,%2,%3}, {%4,%5,%6,%7}, {%8,%9}, {%0,%1,%2,%3};"
        : "+f"(c[0]), "+f"(c[1]), "+f"(c[2]), "+f"(c[3])
        : "r"(a[0]), "r"(a[1]), "r"(a[2]), "r"(a[3]), "r"(b0), "r"(b1));
}

// ============================ dtype detect ============================
__global__ void detect_dtype_kernel(const long long* __restrict__ ei64) {
    int lane = threadIdx.x;
    int bad = 0;
    for (int i = lane; i < 1024; i += 32) {
        long long v = ei64[i];
        if (v < 0 || v >= N_NODES) bad = 1;
    }
    unsigned m = __ballot_sync(0xFFFFFFFFu, bad);
    if (lane == 0) g_is64 = (m == 0u) ? 1 : 0;
}

// ============================ scatter =================================
__global__ void scatter_kernel(const float* __restrict__ x,
                               const void* __restrict__ ei_raw,
                               float* __restrict__ msg,
                               float* __restrict__ deg) {
    int warp = (int)((blockIdx.x * (unsigned)blockDim.x + threadIdx.x) >> 5);
    int lane = threadIdx.x & 31;
    if (warp >= N_EDGES) return;

    long long src, dst;
    if (g_is64) {
        const long long* ei = (const long long*)ei_raw;
        src = ei[warp]; dst = ei[N_EDGES + warp];
    } else {
        const int* ei = (const int*)ei_raw;
        src = ei[warp]; dst = ei[N_EDGES + warp];
    }
    if ((unsigned long long)src >= N_NODES || (unsigned long long)dst >= N_NODES) return;

    float4 v = ((const float4*)(x + (size_t)src * D))[lane];
    float* p = msg + (size_t)dst * D + lane * 4;
    asm volatile("red.global.add.v4.f32 [%0], {%1,%2,%3,%4};"
                 :: "l"(p), "f"(v.x), "f"(v.y), "f"(v.z), "f"(v.w) : "memory");
    if (lane == 0) {
        asm volatile("red.global.add.f32 [%0], %1;"
                     :: "l"(deg + dst), "f"(1.0f) : "memory");
    }
}

// ============================ tf32 mma GEMM ============================
// out = relu( [agg | x] @ [Wl ; Wr]^T + b ), M-tile 128, N=128, K=256.
// Warp tile 32x64 (2 m16-tiles x 8 n8-tiles), K chunked 2x128 through smem.
__global__ __launch_bounds__(256, 1)
void gemm_kernel(const float* __restrict__ x,
                 const float* __restrict__ Wl,
                 const float* __restrict__ bias,
                 const float* __restrict__ Wr,
                 const float* __restrict__ msg,
                 const float* __restrict__ deg,
                 float* __restrict__ out) {
    extern __shared__ float sm[];
    float* sB    = sm;                        // [128][SB_ST]  K = 0..255
    float* sA    = sm + 128 * SB_ST;          // [128][SA_ST]  one K chunk
    float* sBias = sA + 128 * SA_ST;          // [128]

    const int tid = threadIdx.x;
    const int wid = tid >> 5, lid = tid & 31;
    const int grp = lid >> 2, thr = lid & 3;
    const int wm = (wid & 3) * 32;            // warp row base
    const int wn = (wid >> 2) * 64;           // warp col base
    const int n0 = blockIdx.x * GM;

    // --- stage B = [Wl | Wr] as [n][k], k 0..255, tf32-rounded
    for (int idx = tid; idx < 128 * 64; idx += 256) {
        int row = idx >> 6, k0 = (idx & 63) * 4;
        const float* sp = (k0 < 128) ? (Wl + row * 128 + k0)
                                     : (Wr + row * 128 + (k0 - 128));
        float4 v = *(const float4*)sp;
        float* d = sB + row * SB_ST + k0;
        d[0] = to_tf32(v.x); d[1] = to_tf32(v.y);
        d[2] = to_tf32(v.z); d[3] = to_tf32(v.w);
    }
    if (tid < 128) sBias[tid] = bias[tid];

    float acc[2][8][4];
#pragma unroll
    for (int mt = 0; mt < 2; mt++)
#pragma unroll
        for (int nt = 0; nt < 8; nt++)
#pragma unroll
            for (int i = 0; i < 4; i++) acc[mt][nt][i] = 0.f;

    for (int ch = 0; ch < 2; ch++) {
        __syncthreads();   // B/bias ready (ch0); prev-chunk compute done (ch1)
        // --- stage A chunk: ch0 = agg = msg/deg, ch1 = x
        for (int idx = tid; idx < 128 * 32; idx += 256) {
            int row = idx >> 5, k0 = (idx & 31) * 4;
            int g = n0 + row;
            float4 v = make_float4(0.f, 0.f, 0.f, 0.f);
            if (g < N_NODES) {
                if (ch == 0) {
                    float inv = 1.0f / fmaxf(deg[g], 1.0f);
                    float4 m = ((const float4*)(msg + (size_t)g * D))[k0 >> 2];
                    v.x = m.x * inv; v.y = m.y * inv;
                    v.z = m.z * inv; v.w = m.w * inv;
                } else {
                    v = ((const float4*)(x + (size_t)g * D))[k0 >> 2];
                }
            }
            float* d = sA + row * SA_ST + k0;
            d[0] = to_tf32(v.x); d[1] = to_tf32(v.y);
            d[2] = to_tf32(v.z); d[3] = to_tf32(v.w);
        }
        __syncthreads();

        const int kg = ch * 128;
#pragma unroll 4
        for (int ks = 0; ks < 16; ks++) {
            const int k0 = ks * 8;
            uint32_t a[2][4];
#pragma unroll
            for (int mt = 0; mt < 2; mt++) {
                int r0 = wm + mt * 16 + grp;
                a[mt][0] = __float_as_uint(sA[r0 * SA_ST + k0 + thr]);
                a[mt][1] = __float_as_uint(sA[(r0 + 8) * SA_ST + k0 + thr]);
                a[mt][2] = __float_as_uint(sA[r0 * SA_ST + k0 + thr + 4]);
                a[mt][3] = __float_as_uint(sA[(r0 + 8) * SA_ST + k0 + thr + 4]);
            }
#pragma unroll
            for (int nt = 0; nt < 8; nt++) {
                int n = wn + nt * 8 + grp;
                uint32_t b0 = __float_as_uint(sB[n * SB_ST + kg + k0 + thr]);
                uint32_t b1 = __float_as_uint(sB[n * SB_ST + kg + k0 + thr + 4]);
                mma_tf32(acc[0][nt], a[0], b0, b1);
                mma_tf32(acc[1][nt], a[1], b0, b1);
            }
        }
    }

    // --- epilogue: c0/c1 at (row=grp, col=thr*2), c2/c3 at (row=grp+8)
#pragma unroll
    for (int mt = 0; mt < 2; mt++) {
        int rA = n0 + wm + mt * 16 + grp;
        int rB = rA + 8;
#pragma unroll
        for (int nt = 0; nt < 8; nt++) {
            int c = wn + nt * 8 + thr * 2;
            float b0 = sBias[c], b1 = sBias[c + 1];
            if (rA < N_NODES) {
                float2 r;
                r.x = fmaxf(acc[mt][nt][0] + b0, 0.f);
                r.y = fmaxf(acc[mt][nt][1] + b1, 0.f);
                *(float2*)(out + (size_t)rA * D + c) = r;
            }
            if (rB < N_NODES) {
                float2 r;
                r.x = fmaxf(acc[mt][nt][2] + b0, 0.f);
                r.y = fmaxf(acc[mt][nt][3] + b1, 0.f);
                *(float2*)(out + (size_t)rB * D + c) = r;
            }
        }
    }
}

// ============================ launch =================================
extern "C" void kernel_launch(void* const* d_in, const int* in_sizes, int n_in,
                              void* d_out, int out_size) {
    const float* x  = (const float*)d_in[0];
    const void*  ei = d_in[1];
    const float* Wl = (const float*)d_in[2];
    const float* bl = (const float*)d_in[3];
    const float* Wr = (const float*)d_in[4];
    float* out = (float*)d_out;

    float *msg, *deg;
    cudaGetSymbolAddress((void**)&msg, g_msg);
    cudaGetSymbolAddress((void**)&deg, g_deg);

    detect_dtype_kernel<<<1, 32>>>((const long long*)ei);

    cudaMemsetAsync(msg, 0, sizeof(float) * (size_t)N_NODES * D);
    cudaMemsetAsync(deg, 0, sizeof(float) * N_NODES);

    int blocks = (N_EDGES * 32 + 255) / 256;
    scatter_kernel<<<blocks, 256>>>(x, ei, msg, deg);

    int smem = (128 * SB_ST + 128 * SA_ST + 128) * sizeof(float);  // 201216 B
    cudaFuncSetAttribute(gemm_kernel,
                         cudaFuncAttributeMaxDynamicSharedMemorySize, smem);
    int gblocks = (N_NODES + GM - 1) / GM;
    gemm_kernel<<<gblocks, 256, smem>>>(x, Wl, bl, Wr, msg, deg, out);
}

// round 5
// speedup vs baseline: 1.8579x; 1.4234x over previous
#include <cuda_runtime.h>
#include <cstdint>

#define N_NODES 100000
#define N_EDGES 1600000
#define D 128
#define CAP 64            // bin capacity per destination (Poisson(16) tail ~2e-18)
#define GM 128            // nodes per GEMM CTA
#define SB_ST 260
#define SA_ST 132

// ---- scratch (no allocations allowed) ----
__device__ float g_msg[N_NODES * D];       // 51.2 MB
__device__ int   g_cnt[N_NODES];           // degree / bin cursor
__device__ int   g_bin[N_NODES * CAP];     // 25.6 MB
__device__ int   g_is64;

__device__ __forceinline__ float to_tf32(float f) {
    float r; asm("cvt.rna.tf32.f32 %0, %1;" : "=f"(r) : "f"(f)); return r;
}
__device__ __forceinline__ void mma_tf32(float* c, const uint32_t* a,
                                         uint32_t b0, uint32_t b1) {
    asm volatile(
        "mma.sync.aligned.m16n8k8.row.col.f32.tf32.tf32.f32 "
        "{%0,%1,%2,%3}, {%4,%5,%6,%7}, {%8,%9}, {%0,%1,%2,%3};"
        : "+f"(c[0]), "+f"(c[1]), "+f"(c[2]), "+f"(c[3])
        : "r"(a[0]), "r"(a[1]), "r"(a[2]), "r"(a[3]), "r"(b0), "r"(b1));
}

// ============================ dtype detect ============================
__global__ void detect_dtype_kernel(const long long* __restrict__ ei64) {
    int lane = threadIdx.x;
    int bad = 0;
    for (int i = lane; i < 1024; i += 32) {
        long long v = ei64[i];
        if (v < 0 || v >= N_NODES) bad = 1;
    }
    unsigned m = __ballot_sync(0xFFFFFFFFu, bad);
    if (lane == 0) g_is64 = (m == 0u) ? 1 : 0;
}

// ============================ bin edges by dst ========================
__global__ void bin_kernel(const float* __restrict__ x,
                           const void* __restrict__ ei_raw,
                           float* __restrict__ msg) {
    int e = blockIdx.x * blockDim.x + threadIdx.x;
    if (e >= N_EDGES) return;
    int src, dst;
    if (g_is64) {
        const long long* ei = (const long long*)ei_raw;
        src = (int)ei[e]; dst = (int)ei[N_EDGES + e];
    } else {
        const int* ei = (const int*)ei_raw;
        src = ei[e]; dst = ei[N_EDGES + e];
    }
    if ((unsigned)src >= N_NODES || (unsigned)dst >= N_NODES) return;
    int o = atomicAdd(&g_cnt[dst], 1);
    if (o < CAP) {
        g_bin[dst * CAP + o] = src;
    } else {
        // essentially-never fallback: atomic-add full row into msg (msg zeroed)
        const float4* xr = (const float4*)(x + (size_t)src * D);
        float* mp = msg + (size_t)dst * D;
#pragma unroll
        for (int i = 0; i < 32; i++) {
            float4 v = xr[i];
            asm volatile("red.global.add.v4.f32 [%0], {%1,%2,%3,%4};"
                         :: "l"(mp + i * 4), "f"(v.x), "f"(v.y), "f"(v.z), "f"(v.w)
                         : "memory");
        }
    }
}

// ============================ gather-aggregate ========================
// One warp per destination node; lane l owns float4 chunk l of the row.
__global__ void gather_kernel(const float* __restrict__ x,
                              float* __restrict__ msg) {
    int w = (int)((blockIdx.x * (unsigned)blockDim.x + threadIdx.x) >> 5);
    int lane = threadIdx.x & 31;
    if (w >= N_NODES) return;

    int deg = g_cnt[w];
    int n = min(deg, CAP);

    const int* bp = g_bin + (size_t)w * CAP;
    int i0 = (lane < n) ? bp[lane] : 0;
    int i1 = (32 + lane < n) ? bp[32 + lane] : 0;

    float4 acc = make_float4(0.f, 0.f, 0.f, 0.f);
#pragma unroll 4
    for (int i = 0; i < n; i++) {
        int s = (i < 32) ? __shfl_sync(0xFFFFFFFFu, i0, i)
                         : __shfl_sync(0xFFFFFFFFu, i1, i - 32);
        float4 v = __ldg((const float4*)(x + (size_t)s * D) + lane);
        acc.x += v.x; acc.y += v.y; acc.z += v.z; acc.w += v.w;
    }

    float4* mp = (float4*)(msg + (size_t)w * D) + lane;
    if (deg <= CAP) {
        *mp = acc;                       // overwrite: no fallback deposits
    } else {
        float4 m = *mp;                  // add to fallback-deposited partial
        acc.x += m.x; acc.y += m.y; acc.z += m.z; acc.w += m.w;
        *mp = acc;
    }
}

// ============================ tf32 mma GEMM ============================
__global__ __launch_bounds__(256, 1)
void gemm_kernel(const float* __restrict__ x,
                 const float* __restrict__ Wl,
                 const float* __restrict__ bias,
                 const float* __restrict__ Wr,
                 const float* __restrict__ msg,
                 const int* __restrict__ cnt,
                 float* __restrict__ out) {
    extern __shared__ float sm[];
    float* sB    = sm;                        // [128][SB_ST]
    float* sA    = sm + 128 * SB_ST;          // [128][SA_ST]
    float* sBias = sA + 128 * SA_ST;          // [128]

    const int tid = threadIdx.x;
    const int wid = tid >> 5, lid = tid & 31;
    const int grp = lid >> 2, thr = lid & 3;
    const int wm = (wid & 3) * 32;
    const int wn = (wid >> 2) * 64;
    const int n0 = blockIdx.x * GM;

    for (int idx = tid; idx < 128 * 64; idx += 256) {
        int row = idx >> 6, k0 = (idx & 63) * 4;
        const float* sp = (k0 < 128) ? (Wl + row * 128 + k0)
                                     : (Wr + row * 128 + (k0 - 128));
        float4 v = *(const float4*)sp;
        float* d = sB + row * SB_ST + k0;
        d[0] = to_tf32(v.x); d[1] = to_tf32(v.y);
        d[2] = to_tf32(v.z); d[3] = to_tf32(v.w);
    }
    if (tid < 128) sBias[tid] = bias[tid];

    float acc[2][8][4];
#pragma unroll
    for (int mt = 0; mt < 2; mt++)
#pragma unroll
        for (int nt = 0; nt < 8; nt++)
#pragma unroll
            for (int i = 0; i < 4; i++) acc[mt][nt][i] = 0.f;

    for (int ch = 0; ch < 2; ch++) {
        __syncthreads();
        for (int idx = tid; idx < 128 * 32; idx += 256) {
            int row = idx >> 5, k0 = (idx & 31) * 4;
            int g = n0 + row;
            float4 v = make_float4(0.f, 0.f, 0.f, 0.f);
            if (g < N_NODES) {
                if (ch == 0) {
                    float inv = 1.0f / fmaxf((float)cnt[g], 1.0f);
                    float4 m = ((const float4*)(msg + (size_t)g * D))[k0 >> 2];
                    v.x = m.x * inv; v.y = m.y * inv;
                    v.z = m.z * inv; v.w = m.w * inv;
                } else {
                    v = ((const float4*)(x + (size_t)g * D))[k0 >> 2];
                }
            }
            float* d = sA + row * SA_ST + k0;
            d[0] = to_tf32(v.x); d[1] = to_tf32(v.y);
            d[2] = to_tf32(v.z); d[3] = to_tf32(v.w);
        }
        __syncthreads();

        const int kg = ch * 128;
#pragma unroll 4
        for (int ks = 0; ks < 16; ks++) {
            const int k0 = ks * 8;
            uint32_t a[2][4];
#pragma unroll
            for (int mt = 0; mt < 2; mt++) {
                int r0 = wm + mt * 16 + grp;
                a[mt][0] = __float_as_uint(sA[r0 * SA_ST + k0 + thr]);
                a[mt][1] = __float_as_uint(sA[(r0 + 8) * SA_ST + k0 + thr]);
                a[mt][2] = __float_as_uint(sA[r0 * SA_ST + k0 + thr + 4]);
                a[mt][3] = __float_as_uint(sA[(r0 + 8) * SA_ST + k0 + thr + 4]);
            }
#pragma unroll
            for (int nt = 0; nt < 8; nt++) {
                int n = wn + nt * 8 + grp;
                uint32_t b0 = __float_as_uint(sB[n * SB_ST + kg + k0 + thr]);
                uint32_t b1 = __float_as_uint(sB[n * SB_ST + kg + k0 + thr + 4]);
                mma_tf32(acc[0][nt], a[0], b0, b1);
                mma_tf32(acc[1][nt], a[1], b0, b1);
            }
        }
    }

#pragma unroll
    for (int mt = 0; mt < 2; mt++) {
        int rA = n0 + wm + mt * 16 + grp;
        int rB = rA + 8;
#pragma unroll
        for (int nt = 0; nt < 8; nt++) {
            int c = wn + nt * 8 + thr * 2;
            float b0 = sBias[c], b1 = sBias[c + 1];
            if (rA < N_NODES) {
                float2 r;
                r.x = fmaxf(acc[mt][nt][0] + b0, 0.f);
                r.y = fmaxf(acc[mt][nt][1] + b1, 0.f);
                *(float2*)(out + (size_t)rA * D + c) = r;
            }
            if (rB < N_NODES) {
                float2 r;
                r.x = fmaxf(acc[mt][nt][2] + b0, 0.f);
                r.y = fmaxf(acc[mt][nt][3] + b1, 0.f);
                *(float2*)(out + (size_t)rB * D + c) = r;
            }
        }
    }
}

// ============================ launch =================================
extern "C" void kernel_launch(void* const* d_in, const int* in_sizes, int n_in,
                              void* d_out, int out_size) {
    const float* x  = (const float*)d_in[0];
    const void*  ei = d_in[1];
    const float* Wl = (const float*)d_in[2];
    const float* bl = (const float*)d_in[3];
    const float* Wr = (const float*)d_in[4];
    float* out = (float*)d_out;

    float* msg; int* cnt;
    cudaGetSymbolAddress((void**)&msg, g_msg);
    cudaGetSymbolAddress((void**)&cnt, g_cnt);

    detect_dtype_kernel<<<1, 32>>>((const long long*)ei);

    cudaMemsetAsync(cnt, 0, sizeof(int) * N_NODES);
    cudaMemsetAsync(msg, 0, sizeof(float) * (size_t)N_NODES * D);  // fallback base

    bin_kernel<<<(N_EDGES + 255) / 256, 256>>>(x, ei, msg);

    gather_kernel<<<(N_NODES * 32 + 255) / 256, 256>>>(x, msg);

    int smem = (128 * SB_ST + 128 * SA_ST + 128) * sizeof(float);
    cudaFuncSetAttribute(gemm_kernel,
                         cudaFuncAttributeMaxDynamicSharedMemorySize, smem);
    int gblocks = (N_NODES + GM - 1) / GM;
    gemm_kernel<<<gblocks, 256, smem>>>(x, Wl, bl, Wr, msg, cnt, out);
}

// round 6
// speedup vs baseline: 2.5380x; 1.3661x over previous
#include <cuda_runtime.h>
#include <cstdint>

#define N_NODES 100000
#define N_EDGES 1600000
#define D 128
#define CAP 64            // bin capacity per destination
#define GM 128            // nodes per GEMM CTA
#define AST 68            // smem tile stride (floats): bank(row,k)=(4row+k)%32

// ---- scratch (no allocations allowed) ----
__device__ float g_msg[N_NODES * D];       // agg (pre-scaled, tf32-rounded)
__device__ int   g_cnt[N_NODES];
__device__ int   g_bin[N_NODES * CAP];
__device__ float g_wt[128 * 256];          // [Wl|Wr] tf32-rounded, [n][k]
__device__ int   g_is64;

__device__ __forceinline__ float to_tf32(float f) {
    float r; asm("cvt.rna.tf32.f32 %0, %1;" : "=f"(r) : "f"(f)); return r;
}
__device__ __forceinline__ void mma_tf32(float* c, const uint32_t* a,
                                         uint32_t b0, uint32_t b1) {
    asm volatile(
        "mma.sync.aligned.m16n8k8.row.col.f32.tf32.tf32.f32 "
        "{%0,%1,%2,%3}, {%4,%5,%6,%7}, {%8,%9}, {%0,%1,%2,%3};"
        : "+f"(c[0]), "+f"(c[1]), "+f"(c[2]), "+f"(c[3])
        : "r"(a[0]), "r"(a[1]), "r"(a[2]), "r"(a[3]), "r"(b0), "r"(b1));
}
__device__ __forceinline__ uint32_t smem_u32(const void* p) {
    uint32_t a;
    asm("{ .reg .u64 t; cvta.to.shared.u64 t, %1; cvt.u32.u64 %0, t; }" : "=r"(a) : "l"(p));
    return a;
}
__device__ __forceinline__ void cpa16(uint32_t dst, const void* src) {
    asm volatile("cp.async.cg.shared.global [%0], [%1], 16;" :: "r"(dst), "l"(src));
}
#define CP_COMMIT() asm volatile("cp.async.commit_group;" ::: "memory")
#define CP_WAIT(n)  asm volatile("cp.async.wait_group %0;" :: "n"(n) : "memory")

// ============================ dtype detect ============================
__global__ void detect_dtype_kernel(const long long* __restrict__ ei64) {
    int lane = threadIdx.x;
    int bad = 0;
    for (int i = lane; i < 1024; i += 32) {
        long long v = ei64[i];
        if (v < 0 || v >= N_NODES) bad = 1;
    }
    unsigned m = __ballot_sync(0xFFFFFFFFu, bad);
    if (lane == 0) g_is64 = (m == 0u) ? 1 : 0;
}

// ============================ W convert ===============================
__global__ void wcvt_kernel(const float* __restrict__ Wl,
                            const float* __restrict__ Wr,
                            float* __restrict__ wt) {
    int i = blockIdx.x * 256 + threadIdx.x;
    if (i >= 128 * 256) return;
    int n = i >> 8, k = i & 255;
    float v = (k < 128) ? Wl[n * 128 + k] : Wr[n * 128 + (k - 128)];
    wt[i] = to_tf32(v);
}

// ============================ bin edges by dst ========================
__global__ void bin_kernel(const float* __restrict__ x,
                           const void* __restrict__ ei_raw,
                           float* __restrict__ msg) {
    int e = blockIdx.x * blockDim.x + threadIdx.x;
    if (e >= N_EDGES) return;
    int src, dst;
    if (g_is64) {
        const long long* ei = (const long long*)ei_raw;
        src = (int)ei[e]; dst = (int)ei[N_EDGES + e];
    } else {
        const int* ei = (const int*)ei_raw;
        src = ei[e]; dst = ei[N_EDGES + e];
    }
    if ((unsigned)src >= N_NODES || (unsigned)dst >= N_NODES) return;
    int o = atomicAdd(&g_cnt[dst], 1);
    if (o < CAP) {
        g_bin[dst * CAP + o] = src;
    } else {
        // essentially-never fallback: atomic-add raw row into msg (msg zeroed)
        const float4* xr = (const float4*)(x + (size_t)src * D);
        float* mp = msg + (size_t)dst * D;
#pragma unroll
        for (int i = 0; i < 32; i++) {
            float4 v = xr[i];
            asm volatile("red.global.add.v4.f32 [%0], {%1,%2,%3,%4};"
                         :: "l"(mp + i * 4), "f"(v.x), "f"(v.y), "f"(v.z), "f"(v.w)
                         : "memory");
        }
    }
}

// ============================ gather-aggregate ========================
// One warp per destination; writes agg = tf32_rna(sum / max(deg,1)).
__global__ void gather_kernel(const float* __restrict__ x,
                              float* __restrict__ msg) {
    int w = (int)((blockIdx.x * (unsigned)blockDim.x + threadIdx.x) >> 5);
    int lane = threadIdx.x & 31;
    if (w >= N_NODES) return;

    int deg = g_cnt[w];
    int n = min(deg, CAP);

    const int* bp = g_bin + (size_t)w * CAP;
    int i0 = (lane < n) ? bp[lane] : 0;
    int i1 = (32 + lane < n) ? bp[32 + lane] : 0;

    float4 acc = make_float4(0.f, 0.f, 0.f, 0.f);
#pragma unroll 4
    for (int i = 0; i < n; i++) {
        int s = (i < 32) ? __shfl_sync(0xFFFFFFFFu, i0, i)
                         : __shfl_sync(0xFFFFFFFFu, i1, i - 32);
        float4 v = __ldg((const float4*)(x + (size_t)s * D) + lane);
        acc.x += v.x; acc.y += v.y; acc.z += v.z; acc.w += v.w;
    }

    float4* mp = (float4*)(msg + (size_t)w * D) + lane;
    if (deg > CAP) {                     // merge fallback deposits
        float4 m = *mp;
        acc.x += m.x; acc.y += m.y; acc.z += m.z; acc.w += m.w;
    }
    float inv = 1.0f / fmaxf((float)deg, 1.0f);
    acc.x = to_tf32(acc.x * inv); acc.y = to_tf32(acc.y * inv);
    acc.z = to_tf32(acc.z * inv); acc.w = to_tf32(acc.w * inv);
    *mp = acc;
}

// ===================== tf32 mma GEMM, cp.async pipelined ==============
// out = relu( [agg | x] @ wt^T + b ); K = 4 chunks of 64, double-buffered.
__global__ __launch_bounds__(256, 1)
void gemm_kernel(const float* __restrict__ x,
                 const float* __restrict__ wt,
                 const float* __restrict__ bias,
                 const float* __restrict__ msg,
                 float* __restrict__ out) {
    extern __shared__ float sm[];
    float* sB0 = sm;
    float* sB1 = sm + 128 * AST;
    float* sA0 = sm + 2 * 128 * AST;
    float* sA1 = sm + 3 * 128 * AST;
    float* sBias = sm + 4 * 128 * AST;

    const int tid = threadIdx.x;
    const int wid = tid >> 5, lid = tid & 31;
    const int grp = lid >> 2, thr = lid & 3;
    const int wm = (wid & 3) * 32;
    const int wn = (wid >> 2) * 64;
    const int n0 = blockIdx.x * GM;

    const uint32_t sb_u[2] = { smem_u32(sB0), smem_u32(sB1) };
    const uint32_t sa_u[2] = { smem_u32(sA0), smem_u32(sA1) };
    float* const sBp[2] = { sB0, sB1 };
    float* const sAp[2] = { sA0, sA1 };

    if (tid < 128) sBias[tid] = bias[tid];

    // stage chunk c into buffer b: 128 rows x 64 k, 16 cp.async per thread
    auto stage = [&](int b, int c) {
#pragma unroll
        for (int i = 0; i < 8; i++) {
            int idx = tid + i * 256;           // 0..2047
            int row = idx >> 4;
            int k = (idx & 15) * 4;
            uint32_t so = (uint32_t)(row * AST + k) * 4u;
            // B from pre-converted wt
            cpa16(sb_u[b] + so, wt + row * 256 + c * 64 + k);
            // A: chunks 0-1 = agg(msg), 2-3 = raw x (HW tf32-truncates)
            int g = min(n0 + row, N_NODES - 1);
            const float* ap = (c < 2)
                ? msg + (size_t)g * D + c * 64 + k
                : x + (size_t)g * D + (c - 2) * 64 + k;
            cpa16(sa_u[b] + so, ap);
        }
    };

    float acc[2][8][4];
#pragma unroll
    for (int mt = 0; mt < 2; mt++)
#pragma unroll
        for (int nt = 0; nt < 8; nt++)
#pragma unroll
            for (int i = 0; i < 4; i++) acc[mt][nt][i] = 0.f;

    stage(0, 0); CP_COMMIT();

    for (int c = 0; c < 4; c++) {
        if (c < 3) { stage((c + 1) & 1, c + 1); CP_COMMIT(); CP_WAIT(1); }
        else       { CP_WAIT(0); }
        __syncthreads();                   // chunk c visible to all warps

        const float* A = sAp[c & 1];
        const float* B = sBp[c & 1];
#pragma unroll
        for (int ks = 0; ks < 8; ks++) {
            const int k0 = ks * 8;
            uint32_t a[2][4];
#pragma unroll
            for (int mt = 0; mt < 2; mt++) {
                int r0 = wm + mt * 16 + grp;
                a[mt][0] = __float_as_uint(A[r0 * AST + k0 + thr]);
                a[mt][1] = __float_as_uint(A[(r0 + 8) * AST + k0 + thr]);
                a[mt][2] = __float_as_uint(A[r0 * AST + k0 + thr + 4]);
                a[mt][3] = __float_as_uint(A[(r0 + 8) * AST + k0 + thr + 4]);
            }
#pragma unroll
            for (int nt = 0; nt < 8; nt++) {
                int n = wn + nt * 8 + grp;
                uint32_t b0 = __float_as_uint(B[n * AST + k0 + thr]);
                uint32_t b1 = __float_as_uint(B[n * AST + k0 + thr + 4]);
                mma_tf32(acc[0][nt], a[0], b0, b1);
                mma_tf32(acc[1][nt], a[1], b0, b1);
            }
        }
        __syncthreads();                   // done reading before restage
    }

    // epilogue: c0/c1 at (row grp, col 2thr), c2/c3 at row grp+8
#pragma unroll
    for (int mt = 0; mt < 2; mt++) {
        int rA = n0 + wm + mt * 16 + grp;
        int rB = rA + 8;
#pragma unroll
        for (int nt = 0; nt < 8; nt++) {
            int c = wn + nt * 8 + thr * 2;
            float b0 = sBias[c], b1 = sBias[c + 1];
            if (rA < N_NODES) {
                float2 r;
                r.x = fmaxf(acc[mt][nt][0] + b0, 0.f);
                r.y = fmaxf(acc[mt][nt][1] + b1, 0.f);
                *(float2*)(out + (size_t)rA * D + c) = r;
            }
            if (rB < N_NODES) {
                float2 r;
                r.x = fmaxf(acc[mt][nt][2] + b0, 0.f);
                r.y = fmaxf(acc[mt][nt][3] + b1, 0.f);
                *(float2*)(out + (size_t)rB * D + c) = r;
            }
        }
    }
}

// ============================ launch =================================
extern "C" void kernel_launch(void* const* d_in, const int* in_sizes, int n_in,
                              void* d_out, int out_size) {
    const float* x  = (const float*)d_in[0];
    const void*  ei = d_in[1];
    const float* Wl = (const float*)d_in[2];
    const float* bl = (const float*)d_in[3];
    const float* Wr = (const float*)d_in[4];
    float* out = (float*)d_out;

    float *msg, *wt; int* cnt;
    cudaGetSymbolAddress((void**)&msg, g_msg);
    cudaGetSymbolAddress((void**)&cnt, g_cnt);
    cudaGetSymbolAddress((void**)&wt, g_wt);

    detect_dtype_kernel<<<1, 32>>>((const long long*)ei);
    wcvt_kernel<<<128, 256>>>(Wl, Wr, wt);

    cudaMemsetAsync(cnt, 0, sizeof(int) * N_NODES);
    cudaMemsetAsync(msg, 0, sizeof(float) * (size_t)N_NODES * D);  // fallback base

    bin_kernel<<<(N_EDGES + 255) / 256, 256>>>(x, ei, msg);
    gather_kernel<<<(N_NODES * 32 + 255) / 256, 256>>>(x, msg);

    int smem = (4 * 128 * AST + 128) * sizeof(float);   // 139776 B
    cudaFuncSetAttribute(gemm_kernel,
                         cudaFuncAttributeMaxDynamicSharedMemorySize, smem);
    int gblocks = (N_NODES + GM - 1) / GM;
    gemm_kernel<<<gblocks, 256, smem>>>(x, wt, bl, msg, out);
}

// round 7
// speedup vs baseline: 2.5855x; 1.0187x over previous
#include <cuda_runtime.h>
#include <cuda_fp16.h>
#include <cstdint>

#define N_NODES 100000
#define N_EDGES 1600000
#define D 128
#define CAP 64            // bin capacity per destination
#define GM 128            // nodes per GEMM CTA
#define AST 36            // smem tile stride (floats): bank=(4row+k)%32, conflict-free
#define NCH 8             // K chunks of 32

// ---- scratch (no allocations allowed) ----
__device__ float  g_msg[N_NODES * D];      // agg (pre-scaled, tf32-rounded)
__device__ int    g_cnt[N_NODES];
__device__ int    g_bin[N_NODES * CAP];
__device__ float  g_wt[128 * 256];         // [Wl|Wr] tf32-rounded, [n][k]
__device__ __half g_xh[N_NODES * D];       // fp16 copy of x for gather
__device__ int    g_is64;

__device__ __forceinline__ float to_tf32(float f) {
    float r; asm("cvt.rna.tf32.f32 %0, %1;" : "=f"(r) : "f"(f)); return r;
}
__device__ __forceinline__ void mma_tf32(float* c, const uint32_t* a,
                                         uint32_t b0, uint32_t b1) {
    asm volatile(
        "mma.sync.aligned.m16n8k8.row.col.f32.tf32.tf32.f32 "
        "{%0,%1,%2,%3}, {%4,%5,%6,%7}, {%8,%9}, {%0,%1,%2,%3};"
        : "+f"(c[0]), "+f"(c[1]), "+f"(c[2]), "+f"(c[3])
        : "r"(a[0]), "r"(a[1]), "r"(a[2]), "r"(a[3]), "r"(b0), "r"(b1));
}
__device__ __forceinline__ uint32_t smem_u32(const void* p) {
    uint32_t a;
    asm("{ .reg .u64 t; cvta.to.shared.u64 t, %1; cvt.u32.u64 %0, t; }" : "=r"(a) : "l"(p));
    return a;
}
__device__ __forceinline__ void cpa16(uint32_t dst, const void* src) {
    asm volatile("cp.async.cg.shared.global [%0], [%1], 16;" :: "r"(dst), "l"(src));
}
#define CP_COMMIT() asm volatile("cp.async.commit_group;" ::: "memory")
#define CP_WAIT(n)  asm volatile("cp.async.wait_group %0;" :: "n"(n) : "memory")

// ============================ dtype detect ============================
__global__ void detect_dtype_kernel(const long long* __restrict__ ei64) {
    int lane = threadIdx.x;
    int bad = 0;
    for (int i = lane; i < 1024; i += 32) {
        long long v = ei64[i];
        if (v < 0 || v >= N_NODES) bad = 1;
    }
    unsigned m = __ballot_sync(0xFFFFFFFFu, bad);
    if (lane == 0) g_is64 = (m == 0u) ? 1 : 0;
}

// ===================== prep: wt convert + cnt zero + x->fp16 =========
__global__ void prep_kernel(const float* __restrict__ Wl,
                            const float* __restrict__ Wr,
                            const float* __restrict__ x,
                            float* __restrict__ wt,
                            int* __restrict__ cnt,
                            __half2* __restrict__ xh2) {
    int i = blockIdx.x * 256 + threadIdx.x;
    if (i < 128 * 256) {
        int n = i >> 8, k = i & 255;
        float v = (k < 128) ? Wl[n * 128 + k] : Wr[n * 128 + (k - 128)];
        wt[i] = to_tf32(v);
    }
    if (i < N_NODES) cnt[i] = 0;
    if (i < N_NODES * D / 2) {
        float2 v = ((const float2*)x)[i];
        xh2[i] = __floats2half2_rn(v.x, v.y);
    }
}

// ============================ bin edges by dst ========================
__global__ void bin_kernel(const float* __restrict__ x,
                           const void* __restrict__ ei_raw,
                           float* __restrict__ msg) {
    int e = blockIdx.x * blockDim.x + threadIdx.x;
    if (e >= N_EDGES) return;
    int src, dst;
    if (g_is64) {
        const long long* ei = (const long long*)ei_raw;
        src = (int)ei[e]; dst = (int)ei[N_EDGES + e];
    } else {
        const int* ei = (const int*)ei_raw;
        src = ei[e]; dst = ei[N_EDGES + e];
    }
    if ((unsigned)src >= N_NODES || (unsigned)dst >= N_NODES) return;
    int o = atomicAdd(&g_cnt[dst], 1);
    if (o < CAP) {
        g_bin[dst * CAP + o] = src;
    } else {
        // essentially-never fallback: atomic-add raw row into msg (msg zeroed)
        const float4* xr = (const float4*)(x + (size_t)src * D);
        float* mp = msg + (size_t)dst * D;
#pragma unroll
        for (int i = 0; i < 32; i++) {
            float4 v = xr[i];
            asm volatile("red.global.add.v4.f32 [%0], {%1,%2,%3,%4};"
                         :: "l"(mp + i * 4), "f"(v.x), "f"(v.y), "f"(v.z), "f"(v.w)
                         : "memory");
        }
    }
}

// ============================ gather-aggregate ========================
// One warp per destination; lane owns 4 cols. Reads fp16 x-copy (256 B/edge).
__global__ void gather_kernel(const __half* __restrict__ xh,
                              float* __restrict__ msg) {
    int w = (int)((blockIdx.x * (unsigned)blockDim.x + threadIdx.x) >> 5);
    int lane = threadIdx.x & 31;
    if (w >= N_NODES) return;

    int deg = g_cnt[w];
    int n = min(deg, CAP);

    const int* bp = g_bin + (size_t)w * CAP;
    int i0 = (lane < n) ? bp[lane] : 0;
    int i1 = (32 + lane < n) ? bp[32 + lane] : 0;

    float4 acc = make_float4(0.f, 0.f, 0.f, 0.f);
#pragma unroll 4
    for (int i = 0; i < n; i++) {
        int s = (i < 32) ? __shfl_sync(0xFFFFFFFFu, i0, i)
                         : __shfl_sync(0xFFFFFFFFu, i1, i - 32);
        uint2 p = __ldg((const uint2*)(xh + (size_t)s * D) + lane);  // 4 halves
        float2 lo = __half22float2(*(const __half2*)&p.x);
        float2 hi = __half22float2(*(const __half2*)&p.y);
        acc.x += lo.x; acc.y += lo.y; acc.z += hi.x; acc.w += hi.y;
    }

    float4* mp = (float4*)(msg + (size_t)w * D) + lane;
    if (deg > CAP) {                     // merge fallback deposits
        float4 m = *mp;
        acc.x += m.x; acc.y += m.y; acc.z += m.z; acc.w += m.w;
    }
    float inv = 1.0f / fmaxf((float)deg, 1.0f);
    acc.x = to_tf32(acc.x * inv); acc.y = to_tf32(acc.y * inv);
    acc.z = to_tf32(acc.z * inv); acc.w = to_tf32(acc.w * inv);
    *mp = acc;
}

// ===================== tf32 mma GEMM, cp.async pipelined ==============
// out = relu( [agg | x] @ wt^T + b ); K = 8 chunks of 32, double-buffered,
// 2 CTAs/SM.
__global__ __launch_bounds__(256, 2)
void gemm_kernel(const float* __restrict__ x,
                 const float* __restrict__ wt,
                 const float* __restrict__ bias,
                 const float* __restrict__ msg,
                 float* __restrict__ out) {
    extern __shared__ float sm[];
    float* sB0 = sm;
    float* sB1 = sm + 128 * AST;
    float* sA0 = sm + 2 * 128 * AST;
    float* sA1 = sm + 3 * 128 * AST;
    float* sBias = sm + 4 * 128 * AST;

    const int tid = threadIdx.x;
    const int wid = tid >> 5, lid = tid & 31;
    const int grp = lid >> 2, thr = lid & 3;
    const int wm = (wid & 3) * 32;
    const int wn = (wid >> 2) * 64;
    const int n0 = blockIdx.x * GM;

    const uint32_t sb_u[2] = { smem_u32(sB0), smem_u32(sB1) };
    const uint32_t sa_u[2] = { smem_u32(sA0), smem_u32(sA1) };
    float* const sBp[2] = { sB0, sB1 };
    float* const sAp[2] = { sA0, sA1 };

    if (tid < 128) sBias[tid] = bias[tid];

    // stage chunk c (32 k) into buffer b: 4 cp.async x2 per thread
    auto stage = [&](int b, int c) {
#pragma unroll
        for (int i = 0; i < 4; i++) {
            int idx = tid + i * 256;          // 0..1023
            int row = idx >> 3;
            int k = (idx & 7) * 4;
            uint32_t so = (uint32_t)(row * AST + k) * 4u;
            cpa16(sb_u[b] + so, wt + row * 256 + c * 32 + k);
            int g = min(n0 + row, N_NODES - 1);
            const float* ap = (c < 4)
                ? msg + (size_t)g * D + c * 32 + k
                : x + (size_t)g * D + (c - 4) * 32 + k;
            cpa16(sa_u[b] + so, ap);
        }
    };

    float acc[2][8][4];
#pragma unroll
    for (int mt = 0; mt < 2; mt++)
#pragma unroll
        for (int nt = 0; nt < 8; nt++)
#pragma unroll
            for (int i = 0; i < 4; i++) acc[mt][nt][i] = 0.f;

    stage(0, 0); CP_COMMIT();

    for (int c = 0; c < NCH; c++) {
        if (c < NCH - 1) { stage((c + 1) & 1, c + 1); CP_COMMIT(); CP_WAIT(1); }
        else             { CP_WAIT(0); }
        __syncthreads();

        const float* A = sAp[c & 1];
        const float* B = sBp[c & 1];
#pragma unroll
        for (int ks = 0; ks < 4; ks++) {
            const int k0 = ks * 8;
            uint32_t a[2][4];
#pragma unroll
            for (int mt = 0; mt < 2; mt++) {
                int r0 = wm + mt * 16 + grp;
                a[mt][0] = __float_as_uint(A[r0 * AST + k0 + thr]);
                a[mt][1] = __float_as_uint(A[(r0 + 8) * AST + k0 + thr]);
                a[mt][2] = __float_as_uint(A[r0 * AST + k0 + thr + 4]);
                a[mt][3] = __float_as_uint(A[(r0 + 8) * AST + k0 + thr + 4]);
            }
#pragma unroll
            for (int nt = 0; nt < 8; nt++) {
                int n = wn + nt * 8 + grp;
                uint32_t b0 = __float_as_uint(B[n * AST + k0 + thr]);
                uint32_t b1 = __float_as_uint(B[n * AST + k0 + thr + 4]);
                mma_tf32(acc[0][nt], a[0], b0, b1);
                mma_tf32(acc[1][nt], a[1], b0, b1);
            }
        }
        __syncthreads();
    }

    // epilogue
#pragma unroll
    for (int mt = 0; mt < 2; mt++) {
        int rA = n0 + wm + mt * 16 + grp;
        int rB = rA + 8;
#pragma unroll
        for (int nt = 0; nt < 8; nt++) {
            int c = wn + nt * 8 + thr * 2;
            float b0 = sBias[c], b1 = sBias[c + 1];
            if (rA < N_NODES) {
                float2 r;
                r.x = fmaxf(acc[mt][nt][0] + b0, 0.f);
                r.y = fmaxf(acc[mt][nt][1] + b1, 0.f);
                *(float2*)(out + (size_t)rA * D + c) = r;
            }
            if (rB < N_NODES) {
                float2 r;
                r.x = fmaxf(acc[mt][nt][2] + b0, 0.f);
                r.y = fmaxf(acc[mt][nt][3] + b1, 0.f);
                *(float2*)(out + (size_t)rB * D + c) = r;
            }
        }
    }
}

// ============================ launch =================================
extern "C" void kernel_launch(void* const* d_in, const int* in_sizes, int n_in,
                              void* d_out, int out_size) {
    const float* x  = (const float*)d_in[0];
    const void*  ei = d_in[1];
    const float* Wl = (const float*)d_in[2];
    const float* bl = (const float*)d_in[3];
    const float* Wr = (const float*)d_in[4];
    float* out = (float*)d_out;

    float *msg, *wt; int* cnt; __half* xh;
    cudaGetSymbolAddress((void**)&msg, g_msg);
    cudaGetSymbolAddress((void**)&cnt, g_cnt);
    cudaGetSymbolAddress((void**)&wt, g_wt);
    cudaGetSymbolAddress((void**)&xh, g_xh);

    detect_dtype_kernel<<<1, 32>>>((const long long*)ei);                   // 1
    prep_kernel<<<(N_NODES * D / 2 + 255) / 256, 256>>>(Wl, Wr, x, wt, cnt,
                                                        (__half2*)xh);      // 2
    cudaMemsetAsync(msg, 0, sizeof(float) * (size_t)N_NODES * D);           // 3
    bin_kernel<<<(N_EDGES + 255) / 256, 256>>>(x, ei, msg);                 // 4
    gather_kernel<<<(N_NODES * 32 + 255) / 256, 256>>>(xh, msg);            // 5

    int smem = (4 * 128 * AST + 128) * sizeof(float);   // 74240 B
    cudaFuncSetAttribute(gemm_kernel,
                         cudaFuncAttributeMaxDynamicSharedMemorySize, smem);
    int gblocks = (N_NODES + GM - 1) / GM;
    gemm_kernel<<<gblocks, 256, smem>>>(x, wt, bl, msg, out);               // 6
}

// round 8
// speedup vs baseline: 3.1547x; 1.2201x over previous
#include <cuda_runtime.h>
#include <cuda_fp16.h>
#include <cstdint>

#define N_NODES 100000
#define N_EDGES 1600000
#define D 128
#define CAP 64            // bin capacity per destination
#define GM 128            // nodes per GEMM CTA
#define ASTH 72           // smem tile stride (halves): bank=(36*grp+thr)%32, conflict-free
#define NCH 4             // K chunks of 64 halves

// ---- scratch (no allocations allowed) ----
__device__ __half g_msgh[N_NODES * D];     // agg, fp16
__device__ int    g_cnt[N_NODES];
__device__ int    g_bin[N_NODES * CAP];
__device__ __half g_wth[128 * 256];        // [Wl|Wr] fp16, [n][k]
__device__ __half g_xh[N_NODES * D];       // fp16 copy of x
__device__ int    g_is64;

__device__ __forceinline__ void mma_f16(float* c, const uint32_t* a,
                                        uint32_t b0, uint32_t b1) {
    asm volatile(
        "mma.sync.aligned.m16n8k16.row.col.f32.f16.f16.f32 "
        "{%0,%1,%2,%3}, {%4,%5,%6,%7}, {%8,%9}, {%0,%1,%2,%3};"
        : "+f"(c[0]), "+f"(c[1]), "+f"(c[2]), "+f"(c[3])
        : "r"(a[0]), "r"(a[1]), "r"(a[2]), "r"(a[3]), "r"(b0), "r"(b1));
}
__device__ __forceinline__ uint32_t smem_u32(const void* p) {
    uint32_t a;
    asm("{ .reg .u64 t; cvta.to.shared.u64 t, %1; cvt.u32.u64 %0, t; }" : "=r"(a) : "l"(p));
    return a;
}
__device__ __forceinline__ void cpa16(uint32_t dst, const void* src) {
    asm volatile("cp.async.cg.shared.global [%0], [%1], 16;" :: "r"(dst), "l"(src));
}
#define CP_COMMIT() asm volatile("cp.async.commit_group;" ::: "memory")
#define CP_WAIT(n)  asm volatile("cp.async.wait_group %0;" :: "n"(n) : "memory")

// ============================ dtype detect ============================
__global__ void detect_dtype_kernel(const long long* __restrict__ ei64) {
    int lane = threadIdx.x;
    int bad = 0;
    for (int i = lane; i < 1024; i += 32) {
        long long v = ei64[i];
        if (v < 0 || v >= N_NODES) bad = 1;
    }
    unsigned m = __ballot_sync(0xFFFFFFFFu, bad);
    if (lane == 0) g_is64 = (m == 0u) ? 1 : 0;
}

// ============ prep: W->fp16, cnt zero, x->fp16 ========================
__global__ void prep_kernel(const float* __restrict__ Wl,
                            const float* __restrict__ Wr,
                            const float* __restrict__ x,
                            __half2* __restrict__ wth2,
                            int* __restrict__ cnt,
                            __half2* __restrict__ xh2) {
    int i = blockIdx.x * 256 + threadIdx.x;
    if (i < 128 * 128) {                 // 16384 half2 pairs of W
        int n = i >> 7, k = (i & 127) * 2;
        float a, b;
        if (k < 128) { a = Wl[n * 128 + k];       b = Wl[n * 128 + k + 1]; }
        else         { a = Wr[n * 128 + k - 128]; b = Wr[n * 128 + k - 127]; }
        wth2[i] = __floats2half2_rn(a, b);
    }
    if (i < N_NODES) cnt[i] = 0;
    if (i < N_NODES * D / 2) {
        float2 v = ((const float2*)x)[i];
        xh2[i] = __floats2half2_rn(v.x, v.y);
    }
}

// ============================ bin edges by dst ========================
__global__ void bin_kernel(const float* __restrict__ x,
                           const void* __restrict__ ei_raw,
                           __half* __restrict__ msgh) {
    int e = blockIdx.x * blockDim.x + threadIdx.x;
    if (e >= N_EDGES) return;
    int src, dst;
    if (g_is64) {
        const long long* ei = (const long long*)ei_raw;
        src = (int)ei[e]; dst = (int)ei[N_EDGES + e];
    } else {
        const int* ei = (const int*)ei_raw;
        src = ei[e]; dst = ei[N_EDGES + e];
    }
    if ((unsigned)src >= N_NODES || (unsigned)dst >= N_NODES) return;
    int o = atomicAdd(&g_cnt[dst], 1);
    if (o < CAP) {
        g_bin[dst * CAP + o] = src;
    } else {
        // essentially-never fallback: atomic-add row into fp16 msg (zeroed)
        const float4* xr = (const float4*)(x + (size_t)src * D);
        __half2* mp = (__half2*)(msgh + (size_t)dst * D);
#pragma unroll
        for (int i = 0; i < 32; i++) {
            float4 v = xr[i];
            atomicAdd(mp + i * 2,     __floats2half2_rn(v.x, v.y));
            atomicAdd(mp + i * 2 + 1, __floats2half2_rn(v.z, v.w));
        }
    }
}

// ============================ gather-aggregate ========================
// One warp per destination; lane owns 4 cols; fp32 accumulate, fp16 out.
__global__ void gather_kernel(const __half* __restrict__ xh,
                              __half* __restrict__ msgh) {
    int w = (int)((blockIdx.x * (unsigned)blockDim.x + threadIdx.x) >> 5);
    int lane = threadIdx.x & 31;
    if (w >= N_NODES) return;

    int deg = g_cnt[w];
    int n = min(deg, CAP);

    const int* bp = g_bin + (size_t)w * CAP;
    int i0 = (lane < n) ? bp[lane] : 0;
    int i1 = (32 + lane < n) ? bp[32 + lane] : 0;

    float4 acc = make_float4(0.f, 0.f, 0.f, 0.f);
#pragma unroll 4
    for (int i = 0; i < n; i++) {
        int s = (i < 32) ? __shfl_sync(0xFFFFFFFFu, i0, i)
                         : __shfl_sync(0xFFFFFFFFu, i1, i - 32);
        uint2 p = __ldg((const uint2*)(xh + (size_t)s * D) + lane);
        float2 lo = __half22float2(*(const __half2*)&p.x);
        float2 hi = __half22float2(*(const __half2*)&p.y);
        acc.x += lo.x; acc.y += lo.y; acc.z += hi.x; acc.w += hi.y;
    }

    uint2* mp = (uint2*)(msgh + (size_t)w * D) + lane;
    if (deg > CAP) {                     // merge fallback deposits
        uint2 m = *mp;
        float2 lo = __half22float2(*(const __half2*)&m.x);
        float2 hi = __half22float2(*(const __half2*)&m.y);
        acc.x += lo.x; acc.y += lo.y; acc.z += hi.x; acc.w += hi.y;
    }
    float inv = 1.0f / fmaxf((float)deg, 1.0f);
    __half2 h0 = __floats2half2_rn(acc.x * inv, acc.y * inv);
    __half2 h1 = __floats2half2_rn(acc.z * inv, acc.w * inv);
    uint2 st;
    st.x = *(const uint32_t*)&h0;
    st.y = *(const uint32_t*)&h1;
    *mp = st;
}

// ===================== fp16 mma GEMM, cp.async pipelined ==============
// out = relu( [agg | x] @ wt^T + b ); fp16 inputs, fp32 accumulate.
// K = 4 chunks of 64, double-buffered, 2 CTAs/SM.
__global__ __launch_bounds__(256, 2)
void gemm_kernel(const __half* __restrict__ xh,
                 const __half* __restrict__ wth,
                 const float* __restrict__ bias,
                 const __half* __restrict__ msgh,
                 float* __restrict__ out) {
    extern __shared__ char smc[];
    __half* sB0 = (__half*)smc;
    __half* sB1 = sB0 + 128 * ASTH;
    __half* sA0 = sB1 + 128 * ASTH;
    __half* sA1 = sA0 + 128 * ASTH;
    float* sBias = (float*)(smc + 4 * 128 * ASTH * 2);

    const int tid = threadIdx.x;
    const int wid = tid >> 5, lid = tid & 31;
    const int grp = lid >> 2, thr = lid & 3;
    const int wm = (wid & 3) * 32;
    const int wn = (wid >> 2) * 64;
    const int n0 = blockIdx.x * GM;

    const uint32_t sb_u[2] = { smem_u32(sB0), smem_u32(sB1) };
    const uint32_t sa_u[2] = { smem_u32(sA0), smem_u32(sA1) };
    const __half* const sBp[2] = { sB0, sB1 };
    const __half* const sAp[2] = { sA0, sA1 };

    if (tid < 128) sBias[tid] = bias[tid];

    // stage chunk c (64 halves of K) into buffer b: 4+4 cp.async per thread
    auto stage = [&](int b, int c) {
#pragma unroll
        for (int i = 0; i < 4; i++) {
            int idx = tid + i * 256;          // 0..1023
            int row = idx >> 3;
            int kk = (idx & 7) * 8;           // halves
            uint32_t so = (uint32_t)(row * ASTH + kk) * 2u;
            cpa16(sb_u[b] + so, wth + row * 256 + c * 64 + kk);
            int g = min(n0 + row, N_NODES - 1);
            const __half* ap = (c < 2)
                ? msgh + (size_t)g * D + c * 64 + kk
                : xh + (size_t)g * D + (c - 2) * 64 + kk;
            cpa16(sa_u[b] + so, ap);
        }
    };

    float acc[2][8][4];
#pragma unroll
    for (int mt = 0; mt < 2; mt++)
#pragma unroll
        for (int nt = 0; nt < 8; nt++)
#pragma unroll
            for (int i = 0; i < 4; i++) acc[mt][nt][i] = 0.f;

    stage(0, 0); CP_COMMIT();

    for (int c = 0; c < NCH; c++) {
        if (c < NCH - 1) { stage((c + 1) & 1, c + 1); CP_COMMIT(); CP_WAIT(1); }
        else             { CP_WAIT(0); }
        __syncthreads();

        const __half* A = sAp[c & 1];
        const __half* B = sBp[c & 1];
#pragma unroll
        for (int ks = 0; ks < 4; ks++) {
            const int k0 = ks * 16;
            uint32_t a[2][4];
#pragma unroll
            for (int mt = 0; mt < 2; mt++) {
                int r0 = wm + mt * 16 + grp;
                a[mt][0] = *(const uint32_t*)(A + r0 * ASTH + k0 + thr * 2);
                a[mt][1] = *(const uint32_t*)(A + (r0 + 8) * ASTH + k0 + thr * 2);
                a[mt][2] = *(const uint32_t*)(A + r0 * ASTH + k0 + 8 + thr * 2);
                a[mt][3] = *(const uint32_t*)(A + (r0 + 8) * ASTH + k0 + 8 + thr * 2);
            }
#pragma unroll
            for (int nt = 0; nt < 8; nt++) {
                int n = wn + nt * 8 + grp;
                uint32_t b0 = *(const uint32_t*)(B + n * ASTH + k0 + thr * 2);
                uint32_t b1 = *(const uint32_t*)(B + n * ASTH + k0 + 8 + thr * 2);
                mma_f16(acc[0][nt], a[0], b0, b1);
                mma_f16(acc[1][nt], a[1], b0, b1);
            }
        }
        __syncthreads();
    }

    // epilogue: c0/c1 at (row grp, col 2thr), c2/c3 at row grp+8
#pragma unroll
    for (int mt = 0; mt < 2; mt++) {
        int rA = n0 + wm + mt * 16 + grp;
        int rB = rA + 8;
#pragma unroll
        for (int nt = 0; nt < 8; nt++) {
            int c = wn + nt * 8 + thr * 2;
            float b0 = sBias[c], b1 = sBias[c + 1];
            if (rA < N_NODES) {
                float2 r;
                r.x = fmaxf(acc[mt][nt][0] + b0, 0.f);
                r.y = fmaxf(acc[mt][nt][1] + b1, 0.f);
                *(float2*)(out + (size_t)rA * D + c) = r;
            }
            if (rB < N_NODES) {
                float2 r;
                r.x = fmaxf(acc[mt][nt][2] + b0, 0.f);
                r.y = fmaxf(acc[mt][nt][3] + b1, 0.f);
                *(float2*)(out + (size_t)rB * D + c) = r;
            }
        }
    }
}

// ============================ launch =================================
extern "C" void kernel_launch(void* const* d_in, const int* in_sizes, int n_in,
                              void* d_out, int out_size) {
    const float* x  = (const float*)d_in[0];
    const void*  ei = d_in[1];
    const float* Wl = (const float*)d_in[2];
    const float* bl = (const float*)d_in[3];
    const float* Wr = (const float*)d_in[4];
    float* out = (float*)d_out;

    __half *msgh, *wth, *xh; int* cnt;
    cudaGetSymbolAddress((void**)&msgh, g_msgh);
    cudaGetSymbolAddress((void**)&cnt, g_cnt);
    cudaGetSymbolAddress((void**)&wth, g_wth);
    cudaGetSymbolAddress((void**)&xh, g_xh);

    detect_dtype_kernel<<<1, 32>>>((const long long*)ei);                    // 1
    prep_kernel<<<(N_NODES * D / 2 + 255) / 256, 256>>>(Wl, Wr, x,
                                                        (__half2*)wth, cnt,
                                                        (__half2*)xh);       // 2
    cudaMemsetAsync(msgh, 0, sizeof(__half) * (size_t)N_NODES * D);          // 3
    bin_kernel<<<(N_EDGES + 255) / 256, 256>>>(x, ei, msgh);                 // 4
    gather_kernel<<<(N_NODES * 32 + 255) / 256, 256>>>(xh, msgh);            // 5

    int smem = 4 * 128 * ASTH * 2 + 128 * 4;   // 74240 B
    cudaFuncSetAttribute(gemm_kernel,
                         cudaFuncAttributeMaxDynamicSharedMemorySize, smem);
    int gblocks = (N_NODES + GM - 1) / GM;
    gemm_kernel<<<gblocks, 256, smem>>>(xh, wth, bl, msgh, out);             // 6
}